// round 2
// baseline (speedup 1.0000x reference)
#include <cuda_runtime.h>
#include <math.h>

// Problem constants
#define NROW 4096   // N nodes
#define FDIM 256    // feature dim
#define HH   8      // heads
#define UU   64     // per-head dim
#define CC   512    // U*H
#define NC   520    // CC + HH (numerator cols + denominator cols)

// Device scratch (no allocations allowed)
__device__ float g_h   [NROW * CC];   // h[j, head*64+u]
__device__ float g_hw  [NROW * NC];   // [w*h (512 cols) | w (8 cols)]
__device__ float g_out2[NROW * NC];   // A @ g_hw
__device__ float g_colpart[32 * CC];
__device__ float g_colmean[CC];

// ---------------------------------------------------------------------------
// SGEMM: C[M,Nn] = A[M,K] @ B[K,Nn]
// BM=128, BN=64, BK=8, 256 threads, 8x4 per-thread microtile.
// M % 128 == 0 and K % 8 == 0 assumed; Nn boundary-checked (Nn % 4 == 0).
// ---------------------------------------------------------------------------
__global__ __launch_bounds__(256) void k_sgemm(
    const float* __restrict__ A, const float* __restrict__ B,
    float* __restrict__ C, int M, int Nn, int K)
{
    __shared__ float As[8][128];
    __shared__ float Bs[8][64];

    const int tid = threadIdx.x;
    const int bx = blockIdx.x;   // N tile
    const int by = blockIdx.y;   // M tile

    // A tile load mapping: 128 rows x 8 k  -> one float4 per thread
    const int arow = tid >> 1;
    const int acol = (tid & 1) << 2;
    // B tile load mapping: 8 k-rows x 64 cols -> one float2 per thread
    const int brow = tid >> 5;
    const int bcol = (tid & 31) << 1;

    const int tx = tid & 15;    // 16 col groups * 4
    const int ty = tid >> 4;    // 16 row groups * 8

    const float* Ap = A + (by * 128 + arow) * K + acol;
    const int gb = bx * 64 + bcol;

    float acc[8][4];
#pragma unroll
    for (int i = 0; i < 8; i++)
#pragma unroll
        for (int j = 0; j < 4; j++) acc[i][j] = 0.f;

    for (int k0 = 0; k0 < K; k0 += 8) {
        float4 av = *(const float4*)(Ap + k0);
        As[acol + 0][arow] = av.x;
        As[acol + 1][arow] = av.y;
        As[acol + 2][arow] = av.z;
        As[acol + 3][arow] = av.w;

        float2 bv = make_float2(0.f, 0.f);
        if (gb < Nn) bv = *(const float2*)(B + (k0 + brow) * Nn + gb);
        Bs[brow][bcol]     = bv.x;
        Bs[brow][bcol + 1] = bv.y;

        __syncthreads();

#pragma unroll
        for (int kk = 0; kk < 8; kk++) {
            float rA[8], rB[4];
            *(float4*)&rA[0] = *(const float4*)&As[kk][ty * 8];
            *(float4*)&rA[4] = *(const float4*)&As[kk][ty * 8 + 4];
            *(float4*)&rB[0] = *(const float4*)&Bs[kk][tx * 4];
#pragma unroll
            for (int i = 0; i < 8; i++)
#pragma unroll
                for (int j = 0; j < 4; j++)
                    acc[i][j] = fmaf(rA[i], rB[j], acc[i][j]);
        }
        __syncthreads();
    }

    const int crow0 = by * 128 + ty * 8;
    const int ccol  = bx * 64 + tx * 4;
    if (ccol < Nn) {
#pragma unroll
        for (int i = 0; i < 8; i++) {
            float4 o = make_float4(acc[i][0], acc[i][1], acc[i][2], acc[i][3]);
            *(float4*)(C + (crow0 + i) * Nn + ccol) = o;
        }
    }
}

// ---------------------------------------------------------------------------
// Per-node: e_dst[j,h] = sum_u h[j,h,u]*a_dst[u];  w = exp(e_dst);
// g_hw[j, h*64+u] = w*h ;  g_hw[j, 512+h] = w
// One block per node j; warp w handles head w (2 elements per lane).
// ---------------------------------------------------------------------------
__global__ __launch_bounds__(256) void k_edst(const float* __restrict__ avec)
{
    const int j    = blockIdx.x;
    const int warp = threadIdx.x >> 5;
    const int lane = threadIdx.x & 31;

    const float* hrow = g_h + j * CC + warp * UU;
    const float h0 = hrow[lane];
    const float h1 = hrow[lane + 32];

    // a_dst = a[64 + u]
    float p = h0 * avec[UU + lane] + h1 * avec[UU + 32 + lane];
#pragma unroll
    for (int o = 16; o > 0; o >>= 1)
        p += __shfl_xor_sync(0xffffffffu, p, o);
    // broadcast reduced value (all lanes now hold the full sum after xor tree)
    const float wv = expf(p);

    float* dst = g_hw + j * NC + warp * UU;
    dst[lane]      = wv * h0;
    dst[lane + 32] = wv * h1;
    if (lane == 0) g_hw[j * NC + CC + warp] = wv;
}

// ---------------------------------------------------------------------------
// Deterministic column mean of g_h (fallback for fully-masked rows).
// ---------------------------------------------------------------------------
__global__ __launch_bounds__(512) void k_colmean1()
{
    const int c  = threadIdx.x;       // 0..511
    const int b  = blockIdx.x;        // 0..31
    const int j0 = b * 128;
    float s = 0.f;
    for (int j = 0; j < 128; j++) s += g_h[(j0 + j) * CC + c];
    g_colpart[b * CC + c] = s;
}

__global__ __launch_bounds__(256) void k_colmean2()
{
    const int c = blockIdx.x * 256 + threadIdx.x;   // 0..511
    float s = 0.f;
#pragma unroll
    for (int b = 0; b < 32; b++) s += g_colpart[b * CC + c];
    g_colmean[c] = s * (1.0f / (float)NROW);
}

// ---------------------------------------------------------------------------
// Epilogue: out[i, u*8+h] = relu( num[i,h*64+u] / den[i,h] )
// ---------------------------------------------------------------------------
__global__ __launch_bounds__(256) void k_epilogue(float* __restrict__ out)
{
    const int idx = blockIdx.x * 256 + threadIdx.x;   // i*512 + o
    const int i = idx >> 9;
    const int o = idx & 511;
    const int head = o & 7;
    const int u    = o >> 3;

    const float den = g_out2[i * NC + CC + head];
    float v;
    if (den > 0.f) {
        v = g_out2[i * NC + head * UU + u] / den;
    } else {
        // fully-masked row: reference softmax degenerates to uniform 1/N
        v = g_colmean[head * UU + u];
    }
    out[idx] = fmaxf(v, 0.f);
}

// ---------------------------------------------------------------------------
extern "C" void kernel_launch(void* const* d_in, const int* in_sizes, int n_in,
                              void* d_out, int out_size)
{
    (void)in_sizes; (void)n_in; (void)out_size;
    const float* X    = (const float*)d_in[0];   // [1,4096,256]
    const float* Amat = (const float*)d_in[1];   // [1,4096,4096]
    const float* W    = (const float*)d_in[2];   // [256,512]
    const float* avec = (const float*)d_in[3];   // [128,1]
    float* out = (float*)d_out;                  // [1,4096,512]

    float *ph, *phw, *pout2;
    cudaGetSymbolAddress((void**)&ph,    g_h);
    cudaGetSymbolAddress((void**)&phw,   g_hw);
    cudaGetSymbolAddress((void**)&pout2, g_out2);

    // 1) h = X @ W                       [4096,256] @ [256,512]
    k_sgemm<<<dim3(CC / 64, NROW / 128), 256>>>(X, W, ph, NROW, CC, FDIM);
    // 2) weights + weighted features
    k_edst<<<NROW, 256>>>(avec);
    // 3) fallback column means (deterministic, no atomics)
    k_colmean1<<<32, 512>>>();
    k_colmean2<<<2, 256>>>();
    // 4) Out2 = A @ Hw                   [4096,4096] @ [4096,520]
    k_sgemm<<<dim3((NC + 63) / 64, NROW / 128), 256>>>(Amat, phw, pout2, NROW, NC, NROW);
    // 5) divide + permute + relu
    k_epilogue<<<(NROW * CC) / 256, 256>>>(out);
}

// round 4
// speedup vs baseline: 3.2023x; 3.2023x over previous
#include <cuda_runtime.h>
#include <cuda_bf16.h>
#include <cstdint>
#include <math.h>

// ---------------- problem constants ----------------
#define NROW   4096
#define FDIM   256
#define HH     8
#define UU     64
#define CC     512      // U*H
#define NCREAL 520      // CC + HH
#define NCP    576      // padded to 9 tiles of 64
#define KCAT   768      // K for GEMM1: [Xhi|Xlo|Xhi]

// ---------------- device scratch (no allocs) ----------------
__device__ __nv_bfloat16 gA    [NROW * NROW];   // bf16 adjacency (exact 0/1)
__device__ __nv_bfloat16 gXcat [NROW * KCAT];   // [Xhi|Xlo|Xhi]
__device__ __nv_bfloat16 gWcat [NCP  * KCAT];   // row c: [Whi|Whi|Wlo]; rows 512..575 stay 0
__device__ float         g_h   [NROW * NCP];    // X@W (cols 512..575 = 0)
__device__ float         g_hw  [NROW * NCREAL]; // [w*h (512) | w (8)] fp32
__device__ __nv_bfloat16 gBthi [NCP  * NROW];   // Hw^T hi (rows 520..575 stay 0)
__device__ __nv_bfloat16 gBtlo [NCP  * NROW];   // Hw^T lo
__device__ float         g_out2[NROW * NCP];    // A@Hw
__device__ float         g_colpart[32 * CC];
__device__ float         g_colmean[CC];

// ---------------- helpers ----------------
__device__ __forceinline__ uint32_t smem_to_u32(const void* p) {
    uint32_t a;
    asm("{ .reg .u64 t; cvta.to.shared.u64 t, %1; cvt.u32.u64 %0, t; }" : "=r"(a) : "l"(p));
    return a;
}

#define LDSM_X4(r, addr) \
    asm volatile("ldmatrix.sync.aligned.m8n8.x4.shared.b16 {%0,%1,%2,%3}, [%4];" \
        : "=r"((r)[0]), "=r"((r)[1]), "=r"((r)[2]), "=r"((r)[3]) : "r"(addr))

__device__ __forceinline__ void mma16816(float* d, const uint32_t* a,
                                         uint32_t b0, uint32_t b1) {
    asm volatile(
        "mma.sync.aligned.m16n8k16.row.col.f32.bf16.bf16.f32 "
        "{%0,%1,%2,%3}, {%4,%5,%6,%7}, {%8,%9}, {%0,%1,%2,%3};"
        : "+f"(d[0]), "+f"(d[1]), "+f"(d[2]), "+f"(d[3])
        : "r"(a[0]), "r"(a[1]), "r"(a[2]), "r"(a[3]), "r"(b0), "r"(b1));
}

// ---------------------------------------------------------------------------
// bf16 HMMA GEMM: C[M,N] = A[M,K] @ Bt[N,K]^T  (+ optional second pass with B1)
// Block tile 128x64, BK=64, 256 threads (8 warps, 4x2 grid of 32x32 warp tiles)
// 3-stage cp.async pipeline; smem rows of 128B with XOR-16B swizzle.
// ---------------------------------------------------------------------------
#define STAGE_B 24576        // A 16KB + B 8KB
#define GEMM_SMEM (3 * STAGE_B)

__global__ __launch_bounds__(256, 2) void k_mma_gemm(
    const __nv_bfloat16* __restrict__ A, int lda,
    const __nv_bfloat16* __restrict__ B0, const __nv_bfloat16* __restrict__ B1, int ldb,
    float* __restrict__ C, int ldc, int KT, int nB)
{
    extern __shared__ char smem[];
    const uint32_t sb = smem_to_u32(smem);
    const int tid = threadIdx.x, lane = tid & 31, wid = tid >> 5;
    const int warp_m = wid & 3, warp_n = wid >> 2;
    const int m0 = blockIdx.y * 128, n0 = blockIdx.x * 64;
    const int T = KT * nB;

    auto issue_stage = [&](int t) {
        const int kidx = (t < KT) ? t : t - KT;
        const __nv_bfloat16* Bp = (t < KT) ? B0 : B1;
        const uint32_t so = sb + (t % 3) * STAGE_B;
        const __nv_bfloat16* Ak = A + (size_t)m0 * lda + kidx * 64;
#pragma unroll
        for (int i = 0; i < 4; i++) {
            const int idx = tid + (i << 8), r = idx >> 3, c = idx & 7;
            const void* src = Ak + (size_t)r * lda + c * 8;
            const uint32_t dst = so + r * 128 + ((c ^ (r & 7)) << 4);
            asm volatile("cp.async.cg.shared.global [%0], [%1], 16;" :: "r"(dst), "l"(src));
        }
        const __nv_bfloat16* Bk = Bp + (size_t)n0 * ldb + kidx * 64;
#pragma unroll
        for (int i = 0; i < 2; i++) {
            const int idx = tid + (i << 8), r = idx >> 3, c = idx & 7;
            const void* src = Bk + (size_t)r * ldb + c * 8;
            const uint32_t dst = so + 16384 + r * 128 + ((c ^ (r & 7)) << 4);
            asm volatile("cp.async.cg.shared.global [%0], [%1], 16;" :: "r"(dst), "l"(src));
        }
        asm volatile("cp.async.commit_group;" ::: "memory");
    };

    float acc[2][4][4];
#pragma unroll
    for (int i = 0; i < 2; i++)
#pragma unroll
        for (int n = 0; n < 4; n++)
#pragma unroll
            for (int q = 0; q < 4; q++) acc[i][n][q] = 0.f;

    issue_stage(0);
    issue_stage(1);

    const int rA = warp_m * 32 + (lane & 15);
    const int rB = warp_n * 32 + (lane & 15);
    const int h  = lane >> 4;
    const int xa = rA & 7, xb = rB & 7;

    for (int t = 0; t < T; ++t) {
        asm volatile("cp.async.wait_group 1;" ::: "memory");
        __syncthreads();
        const uint32_t so = sb + (t % 3) * STAGE_B;
        const uint32_t aAddr0 = so + rA * 128;
        const uint32_t bAddr0 = so + 16384 + rB * 128;

#pragma unroll
        for (int ks = 0; ks < 4; ++ks) {
            uint32_t a[2][4], b[2][4];
            const int ch = (2 * ks + h);
#pragma unroll
            for (int i = 0; i < 2; ++i)
                LDSM_X4(a[i], aAddr0 + i * 2048 + (((ch ^ xa)) << 4));
#pragma unroll
            for (int j = 0; j < 2; ++j)
                LDSM_X4(b[j], bAddr0 + j * 2048 + (((ch ^ xb)) << 4));
#pragma unroll
            for (int i = 0; i < 2; ++i)
#pragma unroll
                for (int n = 0; n < 4; ++n)
                    mma16816(acc[i][n], a[i], b[n >> 1][n & 1], b[n >> 1][(n & 1) + 2]);
        }
        if (t + 2 < T) issue_stage(t + 2);
    }

    // epilogue: write fp32 C
    const int gid = lane >> 2, tig = lane & 3;
#pragma unroll
    for (int i = 0; i < 2; ++i) {
        const int row = m0 + warp_m * 32 + i * 16 + gid;
#pragma unroll
        for (int n = 0; n < 4; ++n) {
            const int col = n0 + warp_n * 32 + n * 8 + tig * 2;
            float* Cp = C + (size_t)row * ldc + col;
            float2 v0 = make_float2(acc[i][n][0], acc[i][n][1]);
            float2 v1 = make_float2(acc[i][n][2], acc[i][n][3]);
            *(float2*)Cp = v0;
            *(float2*)(Cp + (size_t)8 * ldc) = v1;
        }
    }
}

// ---------------- small prep kernels ----------------
__global__ __launch_bounds__(256) void k_convA(const float* __restrict__ A)
{
    const size_t idx = (size_t)blockIdx.x * 256 + threadIdx.x;   // 8 elems each
    float4 a = ((const float4*)A)[idx * 2];
    float4 b = ((const float4*)A)[idx * 2 + 1];
    __nv_bfloat162 p0 = __float22bfloat162_rn(make_float2(a.x, a.y));
    __nv_bfloat162 p1 = __float22bfloat162_rn(make_float2(a.z, a.w));
    __nv_bfloat162 p2 = __float22bfloat162_rn(make_float2(b.x, b.y));
    __nv_bfloat162 p3 = __float22bfloat162_rn(make_float2(b.z, b.w));
    uint4 o;
    o.x = *(uint32_t*)&p0; o.y = *(uint32_t*)&p1; o.z = *(uint32_t*)&p2; o.w = *(uint32_t*)&p3;
    ((uint4*)gA)[idx] = o;
}

__global__ __launch_bounds__(256) void k_prepX(const float* __restrict__ X)
{
    const int idx = blockIdx.x * 256 + threadIdx.x;   // 1M
    const int i = idx >> 8, k = idx & 255;
    const float v = X[idx];
    __nv_bfloat16 hi = __float2bfloat16_rn(v);
    __nv_bfloat16 lo = __float2bfloat16_rn(v - __bfloat162float(hi));
    gXcat[i * KCAT + k]       = hi;
    gXcat[i * KCAT + 256 + k] = lo;
    gXcat[i * KCAT + 512 + k] = hi;
}

__global__ __launch_bounds__(256) void k_prepW(const float* __restrict__ W)
{
    const int idx = blockIdx.x * 256 + threadIdx.x;   // 131072
    const int k = idx >> 9, c = idx & 511;
    const float v = W[idx];
    __nv_bfloat16 hi = __float2bfloat16_rn(v);
    __nv_bfloat16 lo = __float2bfloat16_rn(v - __bfloat162float(hi));
    gWcat[c * KCAT + k]       = hi;
    gWcat[c * KCAT + 256 + k] = hi;
    gWcat[c * KCAT + 512 + k] = lo;
}

// w = exp(h . a_dst); write [w*h | w] row-major fp32
__global__ __launch_bounds__(256) void k_edst(const float* __restrict__ avec)
{
    const int j = blockIdx.x, warp = threadIdx.x >> 5, lane = threadIdx.x & 31;
    const float* hrow = g_h + (size_t)j * NCP + warp * UU;
    const float h0 = hrow[lane], h1 = hrow[lane + 32];
    float p = h0 * avec[UU + lane] + h1 * avec[UU + 32 + lane];
#pragma unroll
    for (int o = 16; o > 0; o >>= 1) p += __shfl_xor_sync(0xffffffffu, p, o);
    const float wv = expf(p);
    float* dst = g_hw + (size_t)j * NCREAL + warp * UU;
    dst[lane]      = wv * h0;
    dst[lane + 32] = wv * h1;
    if (lane == 0) g_hw[(size_t)j * NCREAL + CC + warp] = wv;
}

// transpose g_hw[4096,520] -> gBthi/gBtlo[(576),4096] with hi/lo split
__global__ __launch_bounds__(256) void k_trans()
{
    __shared__ float tile[32][33];
    const int c0 = blockIdx.x * 32, j0 = blockIdx.y * 32;
    const int tid = threadIdx.x;
#pragma unroll
    for (int ph = 0; ph < 4; ++ph) {
        int idx = ph * 256 + tid, jr = idx >> 5, cc = idx & 31;
        int c = c0 + cc;
        tile[jr][cc] = (c < NCREAL) ? g_hw[(size_t)(j0 + jr) * NCREAL + c] : 0.f;
    }
    __syncthreads();
#pragma unroll
    for (int ph = 0; ph < 4; ++ph) {
        int idx = ph * 256 + tid, cr = idx >> 5, jc = idx & 31;
        int c = c0 + cr;
        if (c < NCREAL) {
            float v = tile[jc][cr];
            __nv_bfloat16 hi = __float2bfloat16_rn(v);
            __nv_bfloat16 lo = __float2bfloat16_rn(v - __bfloat162float(hi));
            gBthi[(size_t)c * NROW + j0 + jc] = hi;
            gBtlo[(size_t)c * NROW + j0 + jc] = lo;
        }
    }
}

// fallback column means of h (fully-masked rows)
__global__ __launch_bounds__(512) void k_colmean1()
{
    const int c = threadIdx.x, b = blockIdx.x, j0 = b * 128;
    float s = 0.f;
    for (int j = 0; j < 128; j++) s += g_h[(size_t)(j0 + j) * NCP + c];
    g_colpart[b * CC + c] = s;
}
__global__ __launch_bounds__(256) void k_colmean2()
{
    const int c = blockIdx.x * 256 + threadIdx.x;
    float s = 0.f;
#pragma unroll
    for (int b = 0; b < 32; b++) s += g_colpart[b * CC + c];
    g_colmean[c] = s * (1.0f / (float)NROW);
}

// out[i, u*8+h] = relu( num/den )
__global__ __launch_bounds__(256) void k_epilogue(float* __restrict__ out)
{
    const int idx = blockIdx.x * 256 + threadIdx.x;
    const int i = idx >> 9, o = idx & 511;
    const int head = o & 7, u = o >> 3;
    const float den = g_out2[(size_t)i * NCP + CC + head];
    float v;
    if (den > 0.f) v = g_out2[(size_t)i * NCP + head * UU + u] / den;
    else           v = g_colmean[head * UU + u];
    out[idx] = fmaxf(v, 0.f);
}

// ---------------- launcher ----------------
extern "C" void kernel_launch(void* const* d_in, const int* in_sizes, int n_in,
                              void* d_out, int out_size)
{
    (void)in_sizes; (void)n_in; (void)out_size;
    const float* X    = (const float*)d_in[0];
    const float* Amat = (const float*)d_in[1];
    const float* W    = (const float*)d_in[2];
    const float* avec = (const float*)d_in[3];
    float* out = (float*)d_out;

    cudaFuncSetAttribute(k_mma_gemm, cudaFuncAttributeMaxDynamicSharedMemorySize, GEMM_SMEM);

    __nv_bfloat16 *pXcat, *pWcat, *pA, *pBthi, *pBtlo;
    float *ph, *pout2;
    cudaGetSymbolAddress((void**)&pXcat, gXcat);
    cudaGetSymbolAddress((void**)&pWcat, gWcat);
    cudaGetSymbolAddress((void**)&pA,    gA);
    cudaGetSymbolAddress((void**)&pBthi, gBthi);
    cudaGetSymbolAddress((void**)&pBtlo, gBtlo);
    cudaGetSymbolAddress((void**)&ph,    g_h);
    cudaGetSymbolAddress((void**)&pout2, g_out2);

    // prep / conversion
    k_convA<<<(NROW * NROW) / (256 * 8), 256>>>(Amat);
    k_prepX<<<(NROW * FDIM) / 256, 256>>>(X);
    k_prepW<<<(FDIM * CC) / 256, 256>>>(W);

    // GEMM1: h = Xcat @ Wcat^T   (M=4096, N=576pad, K=768)
    k_mma_gemm<<<dim3(NCP / 64, NROW / 128), 256, GEMM_SMEM>>>(
        pXcat, KCAT, pWcat, nullptr, KCAT, ph, NCP, KCAT / 64, 1);

    // weights + weighted features, fallback means, transpose+split
    k_edst<<<NROW, 256>>>(avec);
    k_colmean1<<<32, 512>>>();
    k_colmean2<<<2, 256>>>();
    k_trans<<<dim3(17, 128), 256>>>();

    // GEMM2: Out2 = A @ Hw_hi + A @ Hw_lo  (M=4096, N=576pad, K=4096 x2)
    k_mma_gemm<<<dim3(NCP / 64, NROW / 128), 256, GEMM_SMEM>>>(
        pA, NROW, pBthi, pBtlo, NROW, pout2, NCP, NROW / 64, 2);

    // divide + permute + relu
    k_epilogue<<<(NROW * CC) / 256, 256>>>(out);
}

// round 5
// speedup vs baseline: 3.6468x; 1.1388x over previous
#include <cuda_runtime.h>
#include <cuda_bf16.h>
#include <cstdint>
#include <math.h>

// ---------------- problem constants ----------------
#define NROW   4096
#define FDIM   256
#define HH     8
#define UU     64
#define CC     512      // U*H
#define NCREAL 520      // CC + HH
#define NCP    576      // padded to 9 tiles of 64
#define KCAT   768      // K for GEMM1: [Xhi|Xlo|Xhi]

// ---------------- device scratch (no allocs) ----------------
__device__ __nv_bfloat16 gA    [NROW * NROW];   // bf16 adjacency (exact 0/1)
__device__ __nv_bfloat16 gXcat [NROW * KCAT];   // [Xhi|Xlo|Xhi]
__device__ __nv_bfloat16 gWcat [NCP  * KCAT];   // row c: [Whi|Whi|Wlo]; rows 512..575 stay 0
__device__ float         g_h   [NROW * NCP];    // X@W (cols 512..575 = 0)
__device__ float         g_hw  [NROW * NCREAL]; // [w*h (512) | w (8)] fp32
__device__ __nv_bfloat16 gBthi [NCP  * NROW];   // Hw^T hi (rows 520..575 stay 0)
__device__ __nv_bfloat16 gBtlo [NCP  * NROW];   // Hw^T lo
__device__ float         g_out2[NROW * NCP];    // A@Hw

// ---------------- helpers ----------------
__device__ __forceinline__ uint32_t smem_to_u32(const void* p) {
    uint32_t a;
    asm("{ .reg .u64 t; cvta.to.shared.u64 t, %1; cvt.u32.u64 %0, t; }" : "=r"(a) : "l"(p));
    return a;
}

#define LDSM_X4(r, addr) \
    asm volatile("ldmatrix.sync.aligned.m8n8.x4.shared.b16 {%0,%1,%2,%3}, [%4];" \
        : "=r"((r)[0]), "=r"((r)[1]), "=r"((r)[2]), "=r"((r)[3]) : "r"(addr))

__device__ __forceinline__ void mma16816(float* d, const uint32_t* a,
                                         uint32_t b0, uint32_t b1) {
    asm volatile(
        "mma.sync.aligned.m16n8k16.row.col.f32.bf16.bf16.f32 "
        "{%0,%1,%2,%3}, {%4,%5,%6,%7}, {%8,%9}, {%0,%1,%2,%3};"
        : "+f"(d[0]), "+f"(d[1]), "+f"(d[2]), "+f"(d[3])
        : "r"(a[0]), "r"(a[1]), "r"(a[2]), "r"(a[3]), "r"(b0), "r"(b1));
}

// ---------------------------------------------------------------------------
// bf16 HMMA GEMM: C[M,N] = A[M,K] @ B0t[N,K]^T   (DUAL: += A[M,K] @ B1t[N,K]^T)
// Block tile 128x64, BK=64, 256 threads (8 warps, 4x2 grid of 32x32 warp tiles)
// 3-stage cp.async pipeline; smem rows of 128B with XOR-16B swizzle.
// DUAL fuses the hi/lo B passes per K-chunk: A loaded/ldmatrix'd once.
// ---------------------------------------------------------------------------
#define OFF_B0 16384
#define OFF_B1 24576

template<bool DUAL>
__global__ __launch_bounds__(256, 2) void k_mma_gemm(
    const __nv_bfloat16* __restrict__ A, int lda,
    const __nv_bfloat16* __restrict__ B0, const __nv_bfloat16* __restrict__ B1, int ldb,
    float* __restrict__ C, int ldc, int T)
{
    constexpr int STAGE_B = DUAL ? 32768 : 24576;
    extern __shared__ char smem[];
    const uint32_t sb = smem_to_u32(smem);
    const int tid = threadIdx.x, lane = tid & 31, wid = tid >> 5;
    const int warp_m = wid & 3, warp_n = wid >> 2;
    const int m0 = blockIdx.y * 128, n0 = blockIdx.x * 64;

    auto issue_stage = [&](int t) {
        const uint32_t so = sb + (t % 3) * STAGE_B;
        const __nv_bfloat16* Ak = A + (size_t)m0 * lda + t * 64;
#pragma unroll
        for (int i = 0; i < 4; i++) {
            const int idx = tid + (i << 8), r = idx >> 3, c = idx & 7;
            const void* src = Ak + (size_t)r * lda + c * 8;
            const uint32_t dst = so + r * 128 + ((c ^ (r & 7)) << 4);
            asm volatile("cp.async.cg.shared.global [%0], [%1], 16;" :: "r"(dst), "l"(src));
        }
        const __nv_bfloat16* Bk = B0 + (size_t)n0 * ldb + t * 64;
#pragma unroll
        for (int i = 0; i < 2; i++) {
            const int idx = tid + (i << 8), r = idx >> 3, c = idx & 7;
            const void* src = Bk + (size_t)r * ldb + c * 8;
            const uint32_t dst = so + OFF_B0 + r * 128 + ((c ^ (r & 7)) << 4);
            asm volatile("cp.async.cg.shared.global [%0], [%1], 16;" :: "r"(dst), "l"(src));
        }
        if (DUAL) {
            const __nv_bfloat16* Bk1 = B1 + (size_t)n0 * ldb + t * 64;
#pragma unroll
            for (int i = 0; i < 2; i++) {
                const int idx = tid + (i << 8), r = idx >> 3, c = idx & 7;
                const void* src = Bk1 + (size_t)r * ldb + c * 8;
                const uint32_t dst = so + OFF_B1 + r * 128 + ((c ^ (r & 7)) << 4);
                asm volatile("cp.async.cg.shared.global [%0], [%1], 16;" :: "r"(dst), "l"(src));
            }
        }
        asm volatile("cp.async.commit_group;" ::: "memory");
    };

    float acc[2][4][4];
#pragma unroll
    for (int i = 0; i < 2; i++)
#pragma unroll
        for (int n = 0; n < 4; n++)
#pragma unroll
            for (int q = 0; q < 4; q++) acc[i][n][q] = 0.f;

    issue_stage(0);
    issue_stage(1);

    const int rA = warp_m * 32 + (lane & 15);
    const int rB = warp_n * 32 + (lane & 15);
    const int h  = lane >> 4;
    const int xa = rA & 7, xb = rB & 7;

    for (int t = 0; t < T; ++t) {
        asm volatile("cp.async.wait_group 1;" ::: "memory");
        __syncthreads();
        const uint32_t so = sb + (t % 3) * STAGE_B;
        const uint32_t aAddr0 = so + rA * 128;
        const uint32_t bAddr0 = so + OFF_B0 + rB * 128;
        const uint32_t bAddr1 = so + OFF_B1 + rB * 128;

#pragma unroll
        for (int ks = 0; ks < 4; ++ks) {
            uint32_t a[2][4], b0[2][4], b1[2][4];
            const int ch = (2 * ks + h);
#pragma unroll
            for (int i = 0; i < 2; ++i)
                LDSM_X4(a[i], aAddr0 + i * 2048 + ((ch ^ xa) << 4));
#pragma unroll
            for (int j = 0; j < 2; ++j)
                LDSM_X4(b0[j], bAddr0 + j * 2048 + ((ch ^ xb) << 4));
            if (DUAL) {
#pragma unroll
                for (int j = 0; j < 2; ++j)
                    LDSM_X4(b1[j], bAddr1 + j * 2048 + ((ch ^ xb) << 4));
            }
#pragma unroll
            for (int i = 0; i < 2; ++i)
#pragma unroll
                for (int n = 0; n < 4; ++n)
                    mma16816(acc[i][n], a[i], b0[n >> 1][n & 1], b0[n >> 1][(n & 1) + 2]);
            if (DUAL) {
#pragma unroll
                for (int i = 0; i < 2; ++i)
#pragma unroll
                    for (int n = 0; n < 4; ++n)
                        mma16816(acc[i][n], a[i], b1[n >> 1][n & 1], b1[n >> 1][(n & 1) + 2]);
            }
        }
        if (t + 2 < T) issue_stage(t + 2);
    }

    // epilogue: write fp32 C
    const int gid = lane >> 2, tig = lane & 3;
#pragma unroll
    for (int i = 0; i < 2; ++i) {
        const int row = m0 + warp_m * 32 + i * 16 + gid;
#pragma unroll
        for (int n = 0; n < 4; ++n) {
            const int col = n0 + warp_n * 32 + n * 8 + tig * 2;
            float* Cp = C + (size_t)row * ldc + col;
            *(float2*)Cp = make_float2(acc[i][n][0], acc[i][n][1]);
            *(float2*)(Cp + (size_t)8 * ldc) = make_float2(acc[i][n][2], acc[i][n][3]);
        }
    }
}

// ---------------- small prep kernels ----------------
__global__ __launch_bounds__(256) void k_convA(const float* __restrict__ A)
{
    const size_t idx = (size_t)blockIdx.x * 256 + threadIdx.x;   // 8 elems each
    float4 a = ((const float4*)A)[idx * 2];
    float4 b = ((const float4*)A)[idx * 2 + 1];
    __nv_bfloat162 p0 = __float22bfloat162_rn(make_float2(a.x, a.y));
    __nv_bfloat162 p1 = __float22bfloat162_rn(make_float2(a.z, a.w));
    __nv_bfloat162 p2 = __float22bfloat162_rn(make_float2(b.x, b.y));
    __nv_bfloat162 p3 = __float22bfloat162_rn(make_float2(b.z, b.w));
    uint4 o;
    o.x = *(uint32_t*)&p0; o.y = *(uint32_t*)&p1; o.z = *(uint32_t*)&p2; o.w = *(uint32_t*)&p3;
    ((uint4*)gA)[idx] = o;
}

__global__ __launch_bounds__(256) void k_prepX(const float* __restrict__ X)
{
    const int idx = blockIdx.x * 256 + threadIdx.x;   // 1M
    const int i = idx >> 8, k = idx & 255;
    const float v = X[idx];
    __nv_bfloat16 hi = __float2bfloat16_rn(v);
    __nv_bfloat16 lo = __float2bfloat16_rn(v - __bfloat162float(hi));
    gXcat[i * KCAT + k]       = hi;
    gXcat[i * KCAT + 256 + k] = lo;
    gXcat[i * KCAT + 512 + k] = hi;
}

__global__ __launch_bounds__(256) void k_prepW(const float* __restrict__ W)
{
    const int idx = blockIdx.x * 256 + threadIdx.x;   // 131072
    const int k = idx >> 9, c = idx & 511;
    const float v = W[idx];
    __nv_bfloat16 hi = __float2bfloat16_rn(v);
    __nv_bfloat16 lo = __float2bfloat16_rn(v - __bfloat162float(hi));
    gWcat[c * KCAT + k]       = hi;
    gWcat[c * KCAT + 256 + k] = hi;
    gWcat[c * KCAT + 512 + k] = lo;
}

// w = exp(h . a_dst); write [w*h | w] row-major fp32
__global__ __launch_bounds__(256) void k_edst(const float* __restrict__ avec)
{
    const int j = blockIdx.x, warp = threadIdx.x >> 5, lane = threadIdx.x & 31;
    const float* hrow = g_h + (size_t)j * NCP + warp * UU;
    const float h0 = hrow[lane], h1 = hrow[lane + 32];
    float p = h0 * avec[UU + lane] + h1 * avec[UU + 32 + lane];
#pragma unroll
    for (int o = 16; o > 0; o >>= 1) p += __shfl_xor_sync(0xffffffffu, p, o);
    const float wv = expf(p);
    float* dst = g_hw + (size_t)j * NCREAL + warp * UU;
    dst[lane]      = wv * h0;
    dst[lane + 32] = wv * h1;
    if (lane == 0) g_hw[(size_t)j * NCREAL + CC + warp] = wv;
}

// transpose g_hw[4096,520] -> gBthi/gBtlo[(576),4096] with hi/lo split
__global__ __launch_bounds__(256) void k_trans()
{
    __shared__ float tile[32][33];
    const int c0 = blockIdx.x * 32, j0 = blockIdx.y * 32;
    const int tid = threadIdx.x;
#pragma unroll
    for (int ph = 0; ph < 4; ++ph) {
        int idx = ph * 256 + tid, jr = idx >> 5, cc = idx & 31;
        int c = c0 + cc;
        tile[jr][cc] = (c < NCREAL) ? g_hw[(size_t)(j0 + jr) * NCREAL + c] : 0.f;
    }
    __syncthreads();
#pragma unroll
    for (int ph = 0; ph < 4; ++ph) {
        int idx = ph * 256 + tid, cr = idx >> 5, jc = idx & 31;
        int c = c0 + cr;
        if (c < NCREAL) {
            float v = tile[jc][cr];
            __nv_bfloat16 hi = __float2bfloat16_rn(v);
            __nv_bfloat16 lo = __float2bfloat16_rn(v - __bfloat162float(hi));
            gBthi[(size_t)c * NROW + j0 + jc] = hi;
            gBtlo[(size_t)c * NROW + j0 + jc] = lo;
        }
    }
}

// out[i, u*8+h] = relu( num/den ); fully-masked-row fallback computed on demand
__global__ __launch_bounds__(256) void k_epilogue(float* __restrict__ out)
{
    const int idx = blockIdx.x * 256 + threadIdx.x;
    const int i = idx >> 9, o = idx & 511;
    const int head = o & 7, u = o >> 3;
    const int col = head * UU + u;
    const float den = g_out2[(size_t)i * NCP + CC + head];
    float v;
    if (den > 0.f) {
        v = g_out2[(size_t)i * NCP + col] / den;
    } else {
        // reference softmax over an all-masked row degenerates to uniform 1/N
        float s = 0.f;
        for (int j = 0; j < NROW; ++j) s += g_h[(size_t)j * NCP + col];
        v = s * (1.0f / (float)NROW);
    }
    out[idx] = fmaxf(v, 0.f);
}

// ---------------- launcher ----------------
extern "C" void kernel_launch(void* const* d_in, const int* in_sizes, int n_in,
                              void* d_out, int out_size)
{
    (void)in_sizes; (void)n_in; (void)out_size;
    const float* X    = (const float*)d_in[0];
    const float* Amat = (const float*)d_in[1];
    const float* W    = (const float*)d_in[2];
    const float* avec = (const float*)d_in[3];
    float* out = (float*)d_out;

    cudaFuncSetAttribute(k_mma_gemm<false>, cudaFuncAttributeMaxDynamicSharedMemorySize, 3 * 24576);
    cudaFuncSetAttribute(k_mma_gemm<true>,  cudaFuncAttributeMaxDynamicSharedMemorySize, 3 * 32768);

    __nv_bfloat16 *pXcat, *pWcat, *pA, *pBthi, *pBtlo;
    float *ph, *pout2;
    cudaGetSymbolAddress((void**)&pXcat, gXcat);
    cudaGetSymbolAddress((void**)&pWcat, gWcat);
    cudaGetSymbolAddress((void**)&pA,    gA);
    cudaGetSymbolAddress((void**)&pBthi, gBthi);
    cudaGetSymbolAddress((void**)&pBtlo, gBtlo);
    cudaGetSymbolAddress((void**)&ph,    g_h);
    cudaGetSymbolAddress((void**)&pout2, g_out2);

    // prep / conversion
    k_convA<<<(NROW * NROW) / (256 * 8), 256>>>(Amat);
    k_prepX<<<(NROW * FDIM) / 256, 256>>>(X);
    k_prepW<<<(FDIM * CC) / 256, 256>>>(W);

    // GEMM1: h = Xcat @ Wcat^T   (M=4096, N=576pad, K=768)
    k_mma_gemm<false><<<dim3(NCP / 64, NROW / 128), 256, 3 * 24576>>>(
        pXcat, KCAT, pWcat, nullptr, KCAT, ph, NCP, KCAT / 64);

    // weights + weighted features, transpose+split
    k_edst<<<NROW, 256>>>(avec);
    k_trans<<<dim3(17, 128), 256>>>();

    // GEMM2: Out2 = A @ (Hw_hi + Hw_lo), hi/lo fused per K-chunk (K=4096)
    k_mma_gemm<true><<<dim3(NCP / 64, NROW / 128), 256, 3 * 32768>>>(
        pA, NROW, pBthi, pBtlo, NROW, pout2, NCP, NROW / 64);

    // divide + permute + relu
    k_epilogue<<<(NROW * CC) / 256, 256>>>(out);
}